// round 17
// baseline (speedup 1.0000x reference)
#include <cuda_runtime.h>
#include <cuda_bf16.h>
#include <cstdint>
#include <math.h>

// ---------------- problem constants ----------------
#define BATCH 8
#define NPTS  2048
#define KNN   32
#define EMB   512
#define MBIG  (BATCH*NPTS*KNN)   // 524288
#define MSML  (BATCH*NPTS)       // 16384
#define TILES (MBIG/128)         // 4096
#define BN_EPS 1e-5f
#define INV_MBIG (1.f / (float)MBIG)
#define INV_MSML (1.f / (float)MSML)

#define IDX_OFF  (BATCH*EMB*NPTS)                 // 8388608
#define NBR_OFF  (IDX_OFF + BATCH*NPTS*KNN)       // 8912896

// ---------------- scratch ----------------
__device__ float g_feat[8u  * MBIG];
__device__ float g_y2 [64u  * MBIG];
__device__ float g_y3 [128u * MBIG];
__device__ float g_cat[512u * MSML];
__device__ float g_y5 [512u * MSML];
__device__ __nv_bfloat16 g_w2h[64*64],   g_w2l[64*64];
__device__ __nv_bfloat16 g_w3h[128*64],  g_w3l[128*64];
__device__ __nv_bfloat16 g_w4h[256*128], g_w4l[256*128];
__device__ __nv_bfloat16 g_w5h[512*512], g_w5l[512*512];
__device__ float g_accS[1024], g_accQ[1024];
__device__ float g_M[32];

// ---------------- helpers ----------------
__device__ __forceinline__ uint32_t smem_to_u32(const void* p) {
    uint32_t a;
    asm("{ .reg .u64 t; cvta.to.shared.u64 t, %1; cvt.u32.u64 %0, t; }" : "=r"(a) : "l"(p));
    return a;
}
__device__ __forceinline__ uint32_t packbf(float a, float b) {
    __nv_bfloat162 h = __floats2bfloat162_rn(a, b);
    return *(uint32_t*)&h;
}
__device__ __forceinline__ void ldsm4(uint32_t* r, uint32_t addr) {
    asm volatile("ldmatrix.sync.aligned.m8n8.x4.shared.b16 {%0,%1,%2,%3}, [%4];"
        : "=r"(r[0]), "=r"(r[1]), "=r"(r[2]), "=r"(r[3]) : "r"(addr));
}
__device__ __forceinline__ void mma16816(float* c, const uint32_t* a, uint32_t b0, uint32_t b1) {
    asm volatile("mma.sync.aligned.m16n8k16.row.col.f32.bf16.bf16.f32 "
        "{%0,%1,%2,%3}, {%4,%5,%6,%7}, {%8,%9}, {%0,%1,%2,%3};"
        : "+f"(c[0]), "+f"(c[1]), "+f"(c[2]), "+f"(c[3])
        : "r"(a[0]), "r"(a[1]), "r"(a[2]), "r"(a[3]), "r"(b0), "r"(b1));
}
#define CP_COMMIT() asm volatile("cp.async.commit_group;" ::: "memory")
#define CP_WAIT(n)  asm volatile("cp.async.wait_group %0;" :: "n"(n) : "memory")

__device__ __forceinline__ void bn_affine(float as, float aq, float g, float bta,
                                          float invM, float& sc, float& sh) {
    float mu   = as * invM;
    float var  = aq * invM - mu * mu;
    float rstd = 1.f / sqrtf(var + BN_EPS);
    float s    = g * rstd;
    sc = s;
    sh = bta - mu * s;
}

// ---------------- weight convert A + zero accumulators (fused) --------------
__global__ void wconvA_zero_k(const float* W2, const float* W3,
                              __nv_bfloat16* w2h, __nv_bfloat16* w2l,
                              __nv_bfloat16* w3h, __nv_bfloat16* w3l,
                              float* accS, float* accQ, float* gM)
{
    int i = blockIdx.x * blockDim.x + threadIdx.x;
    if (i < 1024) { accS[i] = 0.f; accQ[i] = 0.f; }
    if (i < 32) gM[i] = 0.f;
    const float* src; __nv_bfloat16 *dh, *dl; int off;
    if      (i < 4096)  { src = W2; dh = w2h; dl = w2l; off = 0; }
    else if (i < 12288) { src = W3; dh = w3h; dl = w3l; off = 4096; }
    else return;
    int j = i - off;
    float w = src[j];
    __nv_bfloat16 h = __float2bfloat16(w);
    dh[j] = h;
    dl[j] = __float2bfloat16(w - __bfloat162float(h));
}
__global__ void wconvB_k(const float* W4, const float* W5,
                         __nv_bfloat16* w4h, __nv_bfloat16* w4l,
                         __nv_bfloat16* w5h, __nv_bfloat16* w5l)
{
    int i = blockIdx.x * blockDim.x + threadIdx.x;
    const float* src; __nv_bfloat16 *dh, *dl; int off;
    if      (i < 32768)  { src = W4; dh = w4h; dl = w4l; off = 0; }
    else if (i < 294912) { src = W5; dh = w5h; dl = w5l; off = 32768; }
    else return;
    int j = i - off;
    float w = src[j];
    __nv_bfloat16 h = __float2bfloat16(w);
    dh[j] = h;
    dl[j] = __float2bfloat16(w - __bfloat162float(h));
}

// ---------------- kNN + fused feat moments ----------------
#define KNN_SMEM ((8192 + 8 * 2112) * 4)
__global__ __launch_bounds__(256)
void knn_kernel(const float* __restrict__ x,
                float* __restrict__ outIdx,
                float* __restrict__ outNbr,
                float* __restrict__ feat,
                float* __restrict__ gM)
{
    extern __shared__ float km[];
    float* px  = km;
    float* py  = km + 2048;
    float* pz  = km + 4096;
    float* pxx = km + 6144;
    float* sdall = km + 8192;

    int tid = threadIdx.x, wid = tid >> 5, lane = tid & 31;
    int b = blockIdx.x >> 8;
    int i = ((blockIdx.x & 255) << 3) + wid;
    const float* xb = x + (size_t)b * 3 * NPTS;

    for (int j = tid; j < NPTS; j += 256) {
        float a0 = xb[j], a1 = xb[NPTS + j], a2 = xb[2 * NPTS + j];
        px[j] = a0; py[j] = a1; pz[j] = a2;
        pxx[j] = a0 * a0 + a1 * a1 + a2 * a2;
    }
    __syncthreads();

    float* sd = sdall + wid * 2112;
    float q0 = px[i], q1 = py[i], q2 = pz[i], qxx = pxx[i];

    #pragma unroll 4
    for (int c = 0; c < 64; c++) {
        int j = c * 32 + lane;
        float dot   = q0 * px[j] + q1 * py[j] + q2 * pz[j];
        float inner = -2.f * dot;
        float t     = (-qxx) - inner;
        sd[c * 33 + lane] = t - pxx[j];
    }
    __syncwarp();

    float cm0 = -3.4e38f, cm1 = -3.4e38f;
    int   al0 = 0, al1 = 0;
    #pragma unroll 4
    for (int e = 0; e < 32; e++) {
        float v0 = sd[lane * 33 + e];
        float v1 = sd[(lane + 32) * 33 + e];
        if (v0 > cm0) { cm0 = v0; al0 = e; }
        if (v1 > cm1) { cm1 = v1; al1 = e; }
    }

    int jsel = 0;
    for (int k = 0; k < KNN; k++) {
        float v; int c;
        if (cm0 >= cm1) { v = cm0; c = lane; } else { v = cm1; c = lane + 32; }
        #pragma unroll
        for (int off = 16; off; off >>= 1) {
            float ov = __shfl_down_sync(0xffffffffu, v, off);
            int   oc = __shfl_down_sync(0xffffffffu, c, off);
            if (ov > v || (ov == v && oc < c)) { v = ov; c = oc; }
        }
        c = __shfl_sync(0xffffffffu, c, 0);
        int owner = c & 31;
        int alo = (c < 32) ? al0 : al1;
        int ml = __shfl_sync(0xffffffffu, alo, owner);
        int j = c * 32 + ml;
        if (lane == k) jsel = j;
        float dv = sd[c * 33 + lane];
        if (lane == ml) { dv = -3.4e38f; sd[c * 33 + ml] = dv; }
        float mv = dv; int mlane = lane;
        #pragma unroll
        for (int off = 16; off; off >>= 1) {
            float omv = __shfl_xor_sync(0xffffffffu, mv, off);
            int   oml = __shfl_xor_sync(0xffffffffu, mlane, off);
            if (omv > mv || (omv == mv && oml < mlane)) { mv = omv; mlane = oml; }
        }
        if (lane == owner) {
            if (c < 32) { cm0 = mv; al0 = mlane; }
            else        { cm1 = mv; al1 = mlane; }
        }
        __syncwarp();
    }

    int bn = b * NPTS + i;
    int m  = bn * KNN + lane;
    int j  = jsel;
    outIdx[m] = (float)(j + b * NPTS);
    float v0 = px[j], v1 = py[j], v2 = pz[j];
    size_t ofs = (size_t)m * 3;
    outNbr[ofs + 0] = v0; outNbr[ofs + 1] = v1; outNbr[ofs + 2] = v2;
    float* fp = feat + (size_t)m * 8;
    fp[0] = v0; fp[1] = v1; fp[2] = v2;
    fp[3] = q0; fp[4] = q1; fp[5] = q2;

    float a[27];
    a[0] = v0; a[1] = v1; a[2] = v2; a[3] = q0; a[4] = q1; a[5] = q2;
    {
        int idx = 6;
        #pragma unroll
        for (int t = 0; t < 6; t++)
            #pragma unroll
            for (int u = t; u < 6; u++) a[idx++] = a[t] * a[u];
    }
    #pragma unroll
    for (int off = 16; off; off >>= 1)
        #pragma unroll
        for (int t = 0; t < 27; t++)
            a[t] += __shfl_down_sync(0xffffffffu, a[t], off);
    __syncthreads();
    float* red = sdall;
    if (lane == 0)
        #pragma unroll
        for (int t = 0; t < 27; t++) red[wid * 27 + t] = a[t];
    __syncthreads();
    if (tid < 27) {
        float s = 0.f;
        #pragma unroll
        for (int w = 0; w < 8; w++) s += red[w * 27 + tid];
        atomicAdd(&gM[tid], s);
    }
}

// ---------------- persistent bf16x3 GEMM (conv2/3/4) -------------------------
template <int NWN, int CIN, bool A_FEAT, bool HAS_ACT, bool IN_MAX, bool OUT_MAX, bool WRITE_Y>
__global__ __launch_bounds__(NWN * 128, NWN == 1 ? 4 : (NWN == 2 ? 2 : 1))
void pg_k(const __nv_bfloat16* __restrict__ Wh, const __nv_bfloat16* __restrict__ Wl,
          const float* __restrict__ X, const float* __restrict__ W1,
          const float* __restrict__ gM,
          const float* __restrict__ accSin, const float* __restrict__ accQin,
          const float* __restrict__ gIn, const float* __restrict__ bIn,
          float* __restrict__ Y, float* __restrict__ catXin, float* __restrict__ catXout,
          float* __restrict__ accS, float* __restrict__ accQ)
{
    constexpr int THREADS = NWN * 128;
    constexpr int NT  = NWN * 64;
    constexpr int NKT = CIN / 64;
    constexpr int AREG = 2048 / THREADS;
    constexpr int OFF_SAL = NKT * 16384;
    constexpr int OFF_SBH = 2 * NKT * 16384;
    constexpr int OFF_SBL = OFF_SBH + NKT * NT * 128;
    constexpr int OFF_AFF = OFF_SBL + NKT * NT * 128;
    constexpr int OFF_W1  = OFF_AFF + 2 * CIN * 4;
    constexpr int OFF_XM  = OFF_W1 + (A_FEAT ? 1536 : 0);
    constexpr int OFF_ST  = OFF_XM + NKT * 256 * 4;

    extern __shared__ __align__(16) uint8_t smem[];
    uint8_t* sAh = smem;
    uint8_t* sAl = smem + OFF_SAL;
    uint8_t* sBh = smem + OFF_SBH;
    uint8_t* sBl = smem + OFF_SBL;
    float* scs  = (float*)(smem + OFF_AFF);
    float* shs  = scs + CIN;
    float* w1s  = (float*)(smem + OFF_W1);
    int*   xmax = (int*)(smem + OFF_XM);
    float* sS   = (float*)(smem + OFF_ST);
    float* sQ   = sS + 4 * NT;

    const int tid  = threadIdx.x;
    const int wid  = tid >> 5;
    const int lane = tid & 31;
    const int m_warp = wid & 3;
    const int n_warp = wid >> 2;

    const uint32_t smem_u = smem_to_u32(smem);
    const uint32_t sAh_u = smem_u;
    const uint32_t sAl_u = smem_u + OFF_SAL;
    const uint32_t sBh_u = smem_u + OFF_SBH;
    const uint32_t sBl_u = smem_u + OFF_SBL;

    const float4* Xv = (const float4*)X;
    const uint4* Whv = (const uint4*)Wh;
    const uint4* Wlv = (const uint4*)Wl;
    constexpr int cinV = CIN / 4;
    constexpr int cinW = CIN / 8;

    for (int idx = tid; idx < NKT * NT * 8; idx += THREADS) {
        int n = idx / (NKT * 8);
        int rem = idx - n * (NKT * 8);
        int kt = rem >> 3, c8 = rem & 7;
        int addr = kt * NT * 128 + n * 128 + ((c8 ^ (n & 7)) << 4);
        size_t g = (size_t)n * cinW + kt * 8 + c8;
        *(uint4*)(sBh + addr) = Whv[g];
        *(uint4*)(sBl + addr) = Wlv[g];
    }
    if (A_FEAT) {
        for (int t = tid; t < 384; t += THREADS) w1s[t] = W1[t];
        if (tid < 64) {
            int o = tid;
            float w[6];
            #pragma unroll
            for (int t = 0; t < 6; t++) w[t] = W1[o * 6 + t];
            float s = 0.f;
            #pragma unroll
            for (int t = 0; t < 6; t++) s += w[t] * gM[t];
            float mu = s * INV_MBIG;
            float qq = 0.f; int idx = 6;
            #pragma unroll
            for (int t = 0; t < 6; t++)
                #pragma unroll
                for (int u = t; u < 6; u++) {
                    float term = w[t] * w[u] * gM[idx++];
                    qq += (t == u) ? term : 2.f * term;
                }
            float var  = qq * INV_MBIG - mu * mu;
            float rstd = 1.f / sqrtf(var + BN_EPS);
            float scale = gIn[o] * rstd;
            scs[o] = scale;
            shs[o] = bIn[o] - mu * scale;
        }
    }
    if (HAS_ACT) {
        for (int ch = tid; ch < CIN; ch += THREADS)
            bn_affine(accSin[ch], accQin[ch], gIn[ch], bIn[ch], INV_MBIG, scs[ch], shs[ch]);
    }
    for (int t = tid; t < NKT * 256; t += THREADS) xmax[t] = 0;
    for (int t = tid; t < 4 * NT; t += THREADS) { sS[t] = 0.f; sQ[t] = 0.f; }
    __syncthreads();

    float4 areg[A_FEAT ? 1 : AREG];
    if (!A_FEAT) {
        int mb = blockIdx.x * 128;
        #pragma unroll
        for (int j = 0; j < AREG; j++) {
            int linear = tid + j * THREADS;
            int row = linear >> 4, ch = linear & 15;
            areg[j] = Xv[(size_t)(mb + row) * cinV + ch];
        }
    }

    for (int t = blockIdx.x; t < TILES; t += gridDim.x) {
        const int mBase = t * 128;

        if (A_FEAT) {
            // thread = row mapping: read feat row ONCE, compute all 64 channels
            const int row = tid;
            const float4* fr = (const float4*)(X + (size_t)(mBase + row) * 8);
            float4 fa = fr[0], fb = fr[1];
            float f0 = fa.x, f1 = fa.y, f2 = fa.z, f3 = fa.w, f4 = fb.x, f5 = fb.y;
            const int xbase = (row >> 5) * 64;
            #pragma unroll
            for (int cg = 0; cg < 16; cg++) {
                float4 v;
                #pragma unroll
                for (int cc = 0; cc < 4; cc++) {
                    const float* w = &w1s[(cg * 4 + cc) * 6];
                    (&v.x)[cc] = w[0]*f0 + w[1]*f1 + w[2]*f2 + w[3]*f3 + w[4]*f4 + w[5]*f5;
                }
                int cb = cg * 4;
                float4 s4 = *(const float4*)(scs + cb);
                float4 t4 = *(const float4*)(shs + cb);
                v.x = fmaxf(fmaf(v.x, s4.x, t4.x), 0.f);
                v.y = fmaxf(fmaf(v.y, s4.y, t4.y), 0.f);
                v.z = fmaxf(fmaf(v.z, s4.z, t4.z), 0.f);
                v.w = fmaxf(fmaf(v.w, s4.w, t4.w), 0.f);
                if (IN_MAX) {
                    atomicMax(&xmax[xbase + cb + 0], __float_as_int(v.x));
                    atomicMax(&xmax[xbase + cb + 1], __float_as_int(v.y));
                    atomicMax(&xmax[xbase + cb + 2], __float_as_int(v.z));
                    atomicMax(&xmax[xbase + cb + 3], __float_as_int(v.w));
                }
                float hx = __bfloat162float(__float2bfloat16(v.x));
                float hy = __bfloat162float(__float2bfloat16(v.y));
                float hz = __bfloat162float(__float2bfloat16(v.z));
                float hw = __bfloat162float(__float2bfloat16(v.w));
                int c = cg >> 1, sub = cg & 1;
                int addr = row * 128 + ((c ^ (row & 7)) << 4) + sub * 8;
                *(uint2*)(sAh + addr) = make_uint2(packbf(v.x, v.y), packbf(v.z, v.w));
                *(uint2*)(sAl + addr) = make_uint2(packbf(v.x - hx, v.y - hy), packbf(v.z - hz, v.w - hw));
            }
        } else {
            // prefetch kt=1 up front (latency covered by kt=0 conversion)
            float4 areg2[NKT > 1 ? AREG : 1];
            if (NKT > 1) {
                #pragma unroll
                for (int j = 0; j < AREG; j++) {
                    int linear = tid + j * THREADS;
                    int row = linear >> 4, ch = linear & 15;
                    areg2[j] = Xv[(size_t)(mBase + row) * cinV + 16 + ch];
                }
            }
            #pragma unroll
            for (int kt = 0; kt < NKT; kt++) {
                #pragma unroll
                for (int j = 0; j < AREG; j++) {
                    int linear = tid + j * THREADS;
                    int row = linear >> 4, ch = linear & 15;
                    float4 v = (kt == 0) ? areg[j] : areg2[j];
                    if (HAS_ACT) {
                        int cb = kt * 64 + ch * 4;
                        float4 s4 = *(const float4*)(scs + cb);
                        float4 t4 = *(const float4*)(shs + cb);
                        v.x = fmaxf(fmaf(v.x, s4.x, t4.x), 0.f);
                        v.y = fmaxf(fmaf(v.y, s4.y, t4.y), 0.f);
                        v.z = fmaxf(fmaf(v.z, s4.z, t4.z), 0.f);
                        v.w = fmaxf(fmaf(v.w, s4.w, t4.w), 0.f);
                    }
                    if (IN_MAX) {
                        int base = kt * 256 + (row >> 5) * 64 + ch * 4;
                        atomicMax(&xmax[base + 0], __float_as_int(v.x));
                        atomicMax(&xmax[base + 1], __float_as_int(v.y));
                        atomicMax(&xmax[base + 2], __float_as_int(v.z));
                        atomicMax(&xmax[base + 3], __float_as_int(v.w));
                    }
                    float hx = __bfloat162float(__float2bfloat16(v.x));
                    float hy = __bfloat162float(__float2bfloat16(v.y));
                    float hz = __bfloat162float(__float2bfloat16(v.z));
                    float hw = __bfloat162float(__float2bfloat16(v.w));
                    int c = ch >> 1, sub = ch & 1;
                    int addr = kt * 16384 + row * 128 + ((c ^ (row & 7)) << 4) + sub * 8;
                    *(uint2*)(sAh + addr) = make_uint2(packbf(v.x, v.y), packbf(v.z, v.w));
                    *(uint2*)(sAl + addr) = make_uint2(packbf(v.x - hx, v.y - hy), packbf(v.z - hz, v.w - hw));
                }
            }
        }
        __syncthreads();

        if (IN_MAX) {
            for (int e = tid; e < NKT * 256; e += THREADS) {
                int kt = e >> 8, p = (e >> 6) & 3, chl = e & 63;
                catXin[(size_t)(t * 4 + p) * 512 + kt * 64 + chl] = __int_as_float(xmax[e]);
                xmax[e] = 0;
            }
        }

        if (!A_FEAT) {
            int tn = t + gridDim.x;
            if (tn < TILES) {
                int mb = tn * 128;
                #pragma unroll
                for (int j = 0; j < AREG; j++) {
                    int linear = tid + j * THREADS;
                    int row = linear >> 4, ch = linear & 15;
                    areg[j] = Xv[(size_t)(mb + row) * cinV + ch];
                }
            }
        }

        float acc[2][8][4];
        #pragma unroll
        for (int mt = 0; mt < 2; mt++)
            #pragma unroll
            for (int nt = 0; nt < 8; nt++)
                #pragma unroll
                for (int v = 0; v < 4; v++) acc[mt][nt][v] = 0.f;

        #pragma unroll
        for (int kt = 0; kt < NKT; kt++) {
            const uint32_t aH = sAh_u + kt * 16384;
            const uint32_t aL = sAl_u + kt * 16384;
            const uint32_t bH = sBh_u + kt * NT * 128;
            const uint32_t bL = sBl_u + kt * NT * 128;
            #pragma unroll
            for (int ks = 0; ks < 4; ks++) {
                uint32_t ah[2][4], al[2][4];
                int chunk = 2 * ks + (lane >> 4);
                #pragma unroll
                for (int mt = 0; mt < 2; mt++) {
                    int r = m_warp * 32 + mt * 16 + (lane & 15);
                    int off = r * 128 + ((chunk ^ (r & 7)) << 4);
                    ldsm4(ah[mt], aH + off);
                    ldsm4(al[mt], aL + off);
                }
                #pragma unroll
                for (int ntp = 0; ntp < 4; ntp++) {
                    uint32_t bh[4], bl[4];
                    int r = n_warp * 64 + ntp * 16 + (lane & 15);
                    int off = r * 128 + ((chunk ^ (r & 7)) << 4);
                    ldsm4(bh, bH + off);
                    ldsm4(bl, bL + off);
                    #pragma unroll
                    for (int mt = 0; mt < 2; mt++) {
                        #pragma unroll
                        for (int nb = 0; nb < 2; nb++) {
                            float* c = acc[mt][2 * ntp + nb];
                            mma16816(c, ah[mt], bh[nb], bh[nb + 2]);
                            mma16816(c, ah[mt], bl[nb], bl[nb + 2]);
                            mma16816(c, al[mt], bh[nb], bh[nb + 2]);
                        }
                    }
                }
            }
        }

        const int q4 = lane & 3;
        #pragma unroll
        for (int nt = 0; nt < 8; nt++) {
            int col = n_warp * 64 + nt * 8 + q4 * 2;
            float se = 0.f, so = 0.f, qe = 0.f, qo = 0.f;
            #pragma unroll
            for (int mt = 0; mt < 2; mt++) {
                float* c = acc[mt][nt];
                if (WRITE_Y) {
                    int r0 = mBase + m_warp * 32 + mt * 16 + (lane >> 2);
                    *(float2*)(Y + (size_t)r0 * NT + col)       = make_float2(c[0], c[1]);
                    *(float2*)(Y + (size_t)(r0 + 8) * NT + col) = make_float2(c[2], c[3]);
                }
                se += c[0] + c[2];  so += c[1] + c[3];
                qe += c[0]*c[0] + c[2]*c[2];
                qo += c[1]*c[1] + c[3]*c[3];
            }
            if (OUT_MAX) {
                float m0 = fmaxf(fmaxf(acc[0][nt][0], acc[0][nt][2]),
                                 fmaxf(acc[1][nt][0], acc[1][nt][2]));
                float m1 = fmaxf(fmaxf(acc[0][nt][1], acc[0][nt][3]),
                                 fmaxf(acc[1][nt][1], acc[1][nt][3]));
                #pragma unroll
                for (int off = 16; off >= 4; off >>= 1) {
                    m0 = fmaxf(m0, __shfl_xor_sync(0xffffffffu, m0, off));
                    m1 = fmaxf(m1, __shfl_xor_sync(0xffffffffu, m1, off));
                }
                if (lane < 4) {
                    int pt = t * 4 + m_warp;
                    int cc = n_warp * 64 + nt * 8 + lane * 2;
                    catXout[(size_t)pt * 512 + cc]     = m0;
                    catXout[(size_t)pt * 512 + cc + 1] = m1;
                }
            }
            #pragma unroll
            for (int off = 16; off >= 4; off >>= 1) {
                se += __shfl_down_sync(0xffffffffu, se, off);
                so += __shfl_down_sync(0xffffffffu, so, off);
                qe += __shfl_down_sync(0xffffffffu, qe, off);
                qo += __shfl_down_sync(0xffffffffu, qo, off);
            }
            if (lane < 4) {
                int chl = n_warp * 64 + nt * 8 + lane * 2;
                sS[m_warp * NT + chl]     += se;
                sS[m_warp * NT + chl + 1] += so;
                sQ[m_warp * NT + chl]     += qe;
                sQ[m_warp * NT + chl + 1] += qo;
            }
        }
        __syncthreads();
    }

    for (int ch = tid; ch < NT; ch += THREADS) {
        float s = 0.f, q = 0.f;
        #pragma unroll
        for (int w = 0; w < 4; w++) { s += sS[w * NT + ch]; q += sQ[w * NT + ch]; }
        atomicAdd(&accS[ch], s);
        atomicAdd(&accQ[ch], q);
    }
}

// ---------------- 512-thread streaming GEMM (conv5) --------------------------
#define G512_SB    32768
#define G512_AFF   163840
#define G512_SMEM  168960
__global__ __launch_bounds__(512, 1)
void conv5_k(const __nv_bfloat16* __restrict__ Wh, const __nv_bfloat16* __restrict__ Wl,
             const float* __restrict__ X,
             const float* __restrict__ accSin, const float* __restrict__ accQin,
             const float* __restrict__ gIn, const float* __restrict__ bIn,
             float* __restrict__ Y, float* __restrict__ accS, float* __restrict__ accQ)
{
    constexpr int Cin = 512, Cout = 512;
    extern __shared__ __align__(16) uint8_t smem[];
    uint8_t* sAh = smem;
    uint8_t* sAl = smem + 16384;
    float* scs  = (float*)(smem + G512_AFF);
    float* shs  = scs + 512;
    float* sS   = (float*)smem;
    float* sQ   = sS + 1024;

    const int tid  = threadIdx.x;
    const int wid  = tid >> 5;
    const int lane = tid & 31;
    const int m_warp = wid & 3;
    const int n_warp = wid >> 2;
    const int mBase = blockIdx.y * 128;
    const int oBase = blockIdx.x * 256;

    const uint32_t smem_u = smem_to_u32(smem);
    const uint32_t sAh_u = smem_u;
    const uint32_t sAl_u = smem_u + 16384;

    const float4* Xv = (const float4*)X;
    const uint4* Whv = (const uint4*)Wh;
    const uint4* Wlv = (const uint4*)Wl;
    const int cinV = Cin >> 2;
    const int cinW = Cin >> 3;
    const int nkt  = Cin >> 6;

    for (int ch = tid; ch < 512; ch += 512) {
        if (ch < 256) { scs[ch] = 1.f; shs[ch] = 0.f; }
        else bn_affine(accSin[ch - 256], accQin[ch - 256], gIn[ch - 256], bIn[ch - 256],
                       INV_MBIG, scs[ch], shs[ch]);
    }

    {
        uint32_t sB0 = smem_u + G512_SB;
        #pragma unroll
        for (int j = 0; j < 4; j++) {
            int linear = tid + j * 512;
            int row = linear >> 3, ch = linear & 7;
            uint32_t addr = sB0 + row * 128 + ((ch ^ (row & 7)) << 4);
            const uint4* sh_ = &Whv[(size_t)(oBase + row) * cinW + ch];
            const uint4* sl_ = &Wlv[(size_t)(oBase + row) * cinW + ch];
            asm volatile("cp.async.cg.shared.global [%0], [%1], 16;" :: "r"(addr), "l"(sh_) : "memory");
            asm volatile("cp.async.cg.shared.global [%0], [%1], 16;" :: "r"(addr + 32768), "l"(sl_) : "memory");
        }
        CP_COMMIT();
    }
    float4 areg[4];
    #pragma unroll
    for (int j = 0; j < 4; j++) {
        int linear = tid + j * 512;
        int row = linear >> 4, ch = linear & 15;
        areg[j] = Xv[(size_t)(mBase + row) * cinV + ch];
    }
    __syncthreads();

    float acc[2][8][4];
    #pragma unroll
    for (int mt = 0; mt < 2; mt++)
        #pragma unroll
        for (int nt = 0; nt < 8; nt++)
            #pragma unroll
            for (int v = 0; v < 4; v++) acc[mt][nt][v] = 0.f;

    for (int kt = 0; kt < nkt; kt++) {
        if (kt + 1 < nkt) {
            uint32_t sBn = smem_u + G512_SB + ((kt + 1) & 1) * 65536;
            #pragma unroll
            for (int j = 0; j < 4; j++) {
                int linear = tid + j * 512;
                int row = linear >> 3, ch = linear & 7;
                uint32_t addr = sBn + row * 128 + ((ch ^ (row & 7)) << 4);
                const uint4* sh_ = &Whv[(size_t)(oBase + row) * cinW + (kt + 1) * 8 + ch];
                const uint4* sl_ = &Wlv[(size_t)(oBase + row) * cinW + (kt + 1) * 8 + ch];
                asm volatile("cp.async.cg.shared.global [%0], [%1], 16;" :: "r"(addr), "l"(sh_) : "memory");
                asm volatile("cp.async.cg.shared.global [%0], [%1], 16;" :: "r"(addr + 32768), "l"(sl_) : "memory");
            }
            CP_COMMIT();
        }

        #pragma unroll
        for (int j = 0; j < 4; j++) {
            int linear = tid + j * 512;
            int row = linear >> 4, ch = linear & 15;
            float4 v = areg[j];
            {
                int cb = kt * 64 + ch * 4;
                float4 s4 = *(const float4*)(scs + cb);
                float4 t4 = *(const float4*)(shs + cb);
                v.x = fmaxf(fmaf(v.x, s4.x, t4.x), 0.f);
                v.y = fmaxf(fmaf(v.y, s4.y, t4.y), 0.f);
                v.z = fmaxf(fmaf(v.z, s4.z, t4.z), 0.f);
                v.w = fmaxf(fmaf(v.w, s4.w, t4.w), 0.f);
            }
            float hx = __bfloat162float(__float2bfloat16(v.x));
            float hy = __bfloat162float(__float2bfloat16(v.y));
            float hz = __bfloat162float(__float2bfloat16(v.z));
            float hw = __bfloat162float(__float2bfloat16(v.w));
            int c = ch >> 1, sub = ch & 1;
            int addr = row * 128 + ((c ^ (row & 7)) << 4) + sub * 8;
            *(uint2*)(sAh + addr) = make_uint2(packbf(v.x, v.y), packbf(v.z, v.w));
            *(uint2*)(sAl + addr) = make_uint2(packbf(v.x - hx, v.y - hy), packbf(v.z - hz, v.w - hw));
        }
        if (kt + 1 < nkt) { CP_WAIT(1); } else { CP_WAIT(0); }
        __syncthreads();

        if (kt + 1 < nkt) {
            #pragma unroll
            for (int j = 0; j < 4; j++) {
                int linear = tid + j * 512;
                int row = linear >> 4, ch = linear & 15;
                areg[j] = Xv[(size_t)(mBase + row) * cinV + (kt + 1) * 16 + ch];
            }
        }

        {
            const uint32_t sBh_u = smem_u + G512_SB + (kt & 1) * 65536;
            const uint32_t sBl_u = sBh_u + 32768;
            #pragma unroll
            for (int ks = 0; ks < 4; ks++) {
                uint32_t ah[2][4], al[2][4];
                int chunk = 2 * ks + (lane >> 4);
                #pragma unroll
                for (int mt = 0; mt < 2; mt++) {
                    int r = m_warp * 32 + mt * 16 + (lane & 15);
                    int off = r * 128 + ((chunk ^ (r & 7)) << 4);
                    ldsm4(ah[mt], sAh_u + off);
                    ldsm4(al[mt], sAl_u + off);
                }
                #pragma unroll
                for (int ntp = 0; ntp < 4; ntp++) {
                    uint32_t bh[4], bl[4];
                    int r = n_warp * 64 + ntp * 16 + (lane & 15);
                    int off = r * 128 + ((chunk ^ (r & 7)) << 4);
                    ldsm4(bh, sBh_u + off);
                    ldsm4(bl, sBl_u + off);
                    #pragma unroll
                    for (int mt = 0; mt < 2; mt++) {
                        #pragma unroll
                        for (int nb = 0; nb < 2; nb++) {
                            float* c = acc[mt][2 * ntp + nb];
                            mma16816(c, ah[mt], bh[nb], bh[nb + 2]);
                            mma16816(c, ah[mt], bl[nb], bl[nb + 2]);
                            mma16816(c, al[mt], bh[nb], bh[nb + 2]);
                        }
                    }
                }
            }
        }
        __syncthreads();
    }

    const int q4 = lane & 3;
    #pragma unroll
    for (int nt = 0; nt < 8; nt++) {
        int col = oBase + n_warp * 64 + nt * 8 + q4 * 2;
        float se = 0.f, so = 0.f, qe = 0.f, qo = 0.f;
        #pragma unroll
        for (int mt = 0; mt < 2; mt++) {
            float* c = acc[mt][nt];
            int r0 = mBase + m_warp * 32 + mt * 16 + (lane >> 2);
            *(float2*)(Y + (size_t)r0 * Cout + col)       = make_float2(c[0], c[1]);
            *(float2*)(Y + (size_t)(r0 + 8) * Cout + col) = make_float2(c[2], c[3]);
            se += c[0] + c[2];  so += c[1] + c[3];
            qe += c[0]*c[0] + c[2]*c[2];
            qo += c[1]*c[1] + c[3]*c[3];
        }
        #pragma unroll
        for (int off = 16; off >= 4; off >>= 1) {
            se += __shfl_down_sync(0xffffffffu, se, off);
            so += __shfl_down_sync(0xffffffffu, so, off);
            qe += __shfl_down_sync(0xffffffffu, qe, off);
            qo += __shfl_down_sync(0xffffffffu, qo, off);
        }
        if (lane < 4) {
            int chl = n_warp * 64 + nt * 8 + lane * 2;
            sS[m_warp * 256 + chl]     = se;
            sS[m_warp * 256 + chl + 1] = so;
            sQ[m_warp * 256 + chl]     = qe;
            sQ[m_warp * 256 + chl + 1] = qo;
        }
    }
    __syncthreads();
    if (tid < 256) {
        float s = 0.f, q = 0.f;
        #pragma unroll
        for (int w = 0; w < 4; w++) { s += sS[w * 256 + tid]; q += sQ[w * 256 + tid]; }
        atomicAdd(&accS[oBase + tid], s);
        atomicAdd(&accQ[oBase + tid], q);
    }
}

// ---------------- output transpose + inline affine5 --------------------------
__global__ void out_t(const float* __restrict__ y5,
                      const float* __restrict__ accS, const float* __restrict__ accQ,
                      const float* __restrict__ g, const float* __restrict__ bta,
                      float* __restrict__ out)
{
    __shared__ float ts[32][33];
    int tx = threadIdx.x, ty = threadIdx.y;
    int n0 = blockIdx.x * 32, ch0 = blockIdx.y * 32, b = blockIdx.z;
    int ch = ch0 + tx;
    float s, t;
    bn_affine(accS[ch], accQ[ch], g[ch], bta[ch], INV_MSML, s, t);
    #pragma unroll
    for (int r = 0; r < 4; r++) {
        int nl = ty * 4 + r;
        int m = b * NPTS + n0 + nl;
        float v = y5[(size_t)m * 512 + ch];
        ts[nl][tx] = fmaxf(fmaf(v, s, t), 0.f);
    }
    __syncthreads();
    #pragma unroll
    for (int r = 0; r < 4; r++) {
        int chl = ty * 4 + r;
        out[(size_t)b * (512 * NPTS) + (size_t)(ch0 + chl) * NPTS + n0 + tx] = ts[tx][chl];
    }
}

// ---------------- launcher ----------------
extern "C" void kernel_launch(void* const* d_in, const int* in_sizes, int n_in,
                              void* d_out, int out_size)
{
    const float* x  = (const float*)d_in[0];
    const float* W1 = (const float*)d_in[1];
    const float* g1 = (const float*)d_in[2];
    const float* b1 = (const float*)d_in[3];
    const float* W2 = (const float*)d_in[4];
    const float* g2 = (const float*)d_in[5];
    const float* b2 = (const float*)d_in[6];
    const float* W3 = (const float*)d_in[7];
    const float* g3 = (const float*)d_in[8];
    const float* b3 = (const float*)d_in[9];
    const float* W4 = (const float*)d_in[10];
    const float* g4 = (const float*)d_in[11];
    const float* b4 = (const float*)d_in[12];
    const float* W5 = (const float*)d_in[13];
    const float* g5 = (const float*)d_in[14];
    const float* b5 = (const float*)d_in[15];

    float* out    = (float*)d_out;
    float* outIdx = out + IDX_OFF;
    float* outNbr = out + NBR_OFF;

    float *feat, *y2, *y3, *cat, *y5, *accS, *accQ, *gM;
    __nv_bfloat16 *w2h, *w2l, *w3h, *w3l, *w4h, *w4l, *w5h, *w5l;
    cudaGetSymbolAddress((void**)&feat, g_feat);
    cudaGetSymbolAddress((void**)&y2,   g_y2);
    cudaGetSymbolAddress((void**)&y3,   g_y3);
    cudaGetSymbolAddress((void**)&cat,  g_cat);
    cudaGetSymbolAddress((void**)&y5,   g_y5);
    cudaGetSymbolAddress((void**)&w2h,  g_w2h);
    cudaGetSymbolAddress((void**)&w2l,  g_w2l);
    cudaGetSymbolAddress((void**)&w3h,  g_w3h);
    cudaGetSymbolAddress((void**)&w3l,  g_w3l);
    cudaGetSymbolAddress((void**)&w4h,  g_w4h);
    cudaGetSymbolAddress((void**)&w4l,  g_w4l);
    cudaGetSymbolAddress((void**)&w5h,  g_w5h);
    cudaGetSymbolAddress((void**)&w5l,  g_w5l);
    cudaGetSymbolAddress((void**)&accS, g_accS);
    cudaGetSymbolAddress((void**)&accQ, g_accQ);
    cudaGetSymbolAddress((void**)&gM,   g_M);

    auto* p2 = pg_k<1, 64,  true,  false, true,  false, true >;
    auto* p3 = pg_k<2, 64,  false, true,  true,  false, true >;
    auto* p4 = pg_k<4, 128, false, true,  true,  true,  false>;
    const int SM2 = 54272, SM3 = 71168, SM4 = 207872;
    cudaFuncSetAttribute(knn_kernel, cudaFuncAttributeMaxDynamicSharedMemorySize, KNN_SMEM);
    cudaFuncSetAttribute(p2, cudaFuncAttributeMaxDynamicSharedMemorySize, SM2);
    cudaFuncSetAttribute(p3, cudaFuncAttributeMaxDynamicSharedMemorySize, SM3);
    cudaFuncSetAttribute(p4, cudaFuncAttributeMaxDynamicSharedMemorySize, SM4);
    cudaFuncSetAttribute(conv5_k, cudaFuncAttributeMaxDynamicSharedMemorySize, G512_SMEM);

    wconvA_zero_k<<<(12288 + 255) / 256, 256>>>(W2, W3, w2h, w2l, w3h, w3l,
                                                accS, accQ, gM);
    knn_kernel<<<2048, 256, KNN_SMEM>>>(x, outIdx, outNbr, feat, gM);
    wconvB_k<<<(294912 + 255) / 256, 256>>>(W4, W5, w4h, w4l, w5h, w5l);

    // launch 3 (profiled): conv2 persistent
    p2<<<592, 128, SM2>>>(w2h, w2l, feat, W1, gM,
                          nullptr, nullptr, g1, b1,
                          y2, cat + 0, nullptr, accS + 64, accQ + 64);

    p3<<<296, 256, SM3>>>(w3h, w3l, y2, nullptr, nullptr,
                          accS + 64, accQ + 64, g2, b2,
                          y3, cat + 64, nullptr, accS + 128, accQ + 128);

    p4<<<148, 512, SM4>>>(w4h, w4l, y3, nullptr, nullptr,
                          accS + 128, accQ + 128, g3, b3,
                          nullptr, cat + 128, cat + 256, accS + 256, accQ + 256);

    conv5_k<<<dim3(2, MSML / 128), 512, G512_SMEM>>>(
        w5h, w5l, cat, accS + 256, accQ + 256, g4, b4,
        y5, accS + 512, accQ + 512);

    out_t<<<dim3(NPTS / 32, 16, BATCH), dim3(32, 8)>>>(
        y5, accS + 512, accQ + 512, g5, b5, out);
}